// round 14
// baseline (speedup 1.0000x reference)
#include <cuda_runtime.h>
#include <cuda_bf16.h>
#include <math.h>

#define B_   2
#define L_   2048
#define D_   1024
#define H_   16
#define DH_  64
#define M_   (B_*L_)      // 4096
#define ZN_  (B_*H_)      // 32
#define PW   20           // proj smem row pitch (uints): 16 data + 4 pad
#define NSTG 3            // cp.async pipeline stages
#define SMEMP (NSTG*4*128*PW*4)
#define MARGIN 45.f       // skip-threshold margin (was 130 = exact-underflow)

// ---- Scratch (no allocations) ----
__device__ unsigned g_Qh[(size_t)ZN_*L_*32];
__device__ unsigned g_Ql[(size_t)ZN_*L_*32];
__device__ unsigned g_Kh[(size_t)ZN_*L_*32];
__device__ unsigned g_Kl[(size_t)ZN_*L_*32];
__device__ float    g_V [(size_t)ZN_*L_*DH_];
__device__ unsigned g_Vth[(size_t)ZN_*DH_*(L_/2)];
__device__ unsigned g_Vtl[(size_t)ZN_*DH_*(L_/2)];
__device__ float    g_O [(size_t)M_*D_];
__device__ unsigned g_Xh[(size_t)3*M_*512];
__device__ unsigned g_Xl[(size_t)3*M_*512];
__device__ unsigned g_Wh[(size_t)3*D_*512];
__device__ unsigned g_Wl[(size_t)3*D_*512];
__device__ float    g_maxK[ZN_];

__device__ __forceinline__ void split2(float x0, float x1, unsigned &hi, unsigned &lo) {
    __nv_bfloat16 h0 = __float2bfloat16(x0);
    __nv_bfloat16 h1 = __float2bfloat16(x1);
    __nv_bfloat16 l0 = __float2bfloat16(x0 - __bfloat162float(h0));
    __nv_bfloat16 l1 = __float2bfloat16(x1 - __bfloat162float(h1));
    hi = ((unsigned)__bfloat16_as_ushort(h1) << 16) | (unsigned)__bfloat16_as_ushort(h0);
    lo = ((unsigned)__bfloat16_as_ushort(l1) << 16) | (unsigned)__bfloat16_as_ushort(l0);
}

__device__ __forceinline__ void mma16816(float* c,
        unsigned a0, unsigned a1, unsigned a2, unsigned a3,
        unsigned b0, unsigned b1) {
    asm volatile(
        "mma.sync.aligned.m16n8k16.row.col.f32.bf16.bf16.f32 "
        "{%0,%1,%2,%3},{%4,%5,%6,%7},{%8,%9},{%0,%1,%2,%3};\n"
        : "+f"(c[0]), "+f"(c[1]), "+f"(c[2]), "+f"(c[3])
        : "r"(a0), "r"(a1), "r"(a2), "r"(a3), "r"(b0), "r"(b1));
}

// ---------------------------------------------------------------------------
// fp32 -> bf16 hi/lo plane splits (device-global destinations)
// ---------------------------------------------------------------------------
__global__ void convsplit_X3(const float* __restrict__ q,
                             const float* __restrict__ k,
                             const float* __restrict__ v) {
    const float* src = (blockIdx.y == 0) ? q : (blockIdx.y == 1) ? k : v;
    const size_t off = (size_t)blockIdx.y * M_ * 512;
    const size_t i = (size_t)blockIdx.x * 256 + threadIdx.x;
    float4 a = *(const float4*)&src[i * 4];
    unsigned h0, l0, h1, l1;
    split2(a.x, a.y, h0, l0);
    split2(a.z, a.w, h1, l1);
    g_Xh[off + 2*i] = h0; g_Xh[off + 2*i+1] = h1;
    g_Xl[off + 2*i] = l0; g_Xl[off + 2*i+1] = l1;
}
__global__ void convsplit_W3(const float* __restrict__ wq,
                             const float* __restrict__ wk,
                             const float* __restrict__ wv) {
    const float* src = (blockIdx.y == 0) ? wq : (blockIdx.y == 1) ? wk : wv;
    const size_t off = (size_t)blockIdx.y * D_ * 512;
    const size_t i = (size_t)blockIdx.x * 256 + threadIdx.x;
    float4 a = *(const float4*)&src[i * 4];
    unsigned h0, l0, h1, l1;
    split2(a.x, a.y, h0, l0);
    split2(a.z, a.w, h1, l1);
    g_Wh[off + 2*i] = h0; g_Wh[off + 2*i+1] = h1;
    g_Wl[off + 2*i] = l0; g_Wl[off + 2*i+1] = l1;
}
__global__ void convsplit_O() {     // g_O -> X planes slot 0
    const size_t i = (size_t)blockIdx.x * 256 + threadIdx.x;
    float4 a = *(const float4*)&g_O[i * 4];
    unsigned h0, l0, h1, l1;
    split2(a.x, a.y, h0, l0);
    split2(a.z, a.w, h1, l1);
    g_Xh[2*i] = h0; g_Xh[2*i+1] = h1;
    g_Xl[2*i] = l0; g_Xl[2*i+1] = l1;
}

// ---------------------------------------------------------------------------
// V transpose + split:  g_V -> g_Vth/g_Vtl [z][d][l/2]
// ---------------------------------------------------------------------------
__global__ void vtrans_kernel() {
    __shared__ float sT[128][65];
    const int tid = threadIdx.x;
    const int z = blockIdx.y;
    const int l0 = blockIdx.x * 128;
    const size_t zq = (size_t)z * L_;
#pragma unroll
    for (int t = 0; t < 32; t++) {
        const int u = t * 256 + tid;
        const int l = u >> 6, d = u & 63;
        sT[l][d] = g_V[(zq + l0 + l) * DH_ + d];
    }
    __syncthreads();
#pragma unroll
    for (int t = 0; t < 16; t++) {
        const int u = t * 256 + tid;
        const int d = u >> 6, lp = u & 63;
        unsigned hi, lo;
        split2(sT[2*lp][d], sT[2*lp+1][d], hi, lo);
        const size_t idx = ((size_t)z * DH_ + d) * (L_/2) + (l0 >> 1) + lp;
        g_Vth[idx] = hi; g_Vtl[idx] = lo;
    }
}

// ---------------------------------------------------------------------------
// Per-z max K-row norm. One block per z.
// ---------------------------------------------------------------------------
__global__ void knorm_kernel() {
    __shared__ float red[256];
    const int tid = threadIdx.x;
    const int z = blockIdx.x;
    const size_t zq = (size_t)z * L_;
    float mx = 0.f;
#pragma unroll
    for (int t = 0; t < 8; t++) {
        const int row = t * 256 + tid;
        float n2 = 0.f;
        const size_t base = (zq + row) * 32;
#pragma unroll
        for (int u = 0; u < 32; u++) {
            __nv_bfloat162 hb = *(const __nv_bfloat162*)&g_Kh[base + u];
            __nv_bfloat162 lb = *(const __nv_bfloat162*)&g_Kl[base + u];
            float v0 = __bfloat162float(hb.x) + __bfloat162float(lb.x);
            float v1 = __bfloat162float(hb.y) + __bfloat162float(lb.y);
            n2 += v0 * v0 + v1 * v1;
        }
        mx = fmaxf(mx, n2);
    }
    red[tid] = mx; __syncthreads();
    for (int s = 128; s > 0; s >>= 1) {
        if (tid < s) red[tid] = fmaxf(red[tid], red[tid + s]);
        __syncthreads();
    }
    if (tid == 0) g_maxK[z] = sqrtf(red[0]);
}

// ---------------------------------------------------------------------------
// cp.async 3-stage pipelined GEMM core on pre-split planes.
// ---------------------------------------------------------------------------
__device__ __forceinline__ unsigned* smbuf(unsigned* sm, int stage, int arr) {
    return sm + ((stage * 4 + arr) * 128 * PW);
}

__device__ __forceinline__ void load_chunk(unsigned* sm, int stage,
        const unsigned* __restrict__ Xh, const unsigned* __restrict__ Xl,
        const unsigned* __restrict__ Wh, const unsigned* __restrict__ Wl,
        int m0, int n0, int ku, int tid) {
#pragma unroll
    for (int t = 0; t < 8; t++) {
        const int u = t * 256 + tid;
        const int arr = u >> 9, rem = u & 511;
        const int row = rem >> 2, c4 = (rem & 3) * 4;
        const unsigned* src;
        if      (arr == 0) src = &Xh[(size_t)(m0 + row) * 512 + ku + c4];
        else if (arr == 1) src = &Xl[(size_t)(m0 + row) * 512 + ku + c4];
        else if (arr == 2) src = &Wh[(size_t)(n0 + row) * 512 + ku + c4];
        else               src = &Wl[(size_t)(n0 + row) * 512 + ku + c4];
        const unsigned dst =
            (unsigned)__cvta_generic_to_shared(smbuf(sm, stage, arr) + row * PW + c4);
        asm volatile("cp.async.cg.shared.global [%0], [%1], 16;" :: "r"(dst), "l"(src));
    }
    asm volatile("cp.async.commit_group;");
}

__device__ __forceinline__ void compute_chunk(unsigned* sm, int stage,
        int wm, int wn, int r, int cq, float acc[4][4][4]) {
    unsigned* A0 = smbuf(sm, stage, 0);
    unsigned* A1 = smbuf(sm, stage, 1);
    unsigned* B0 = smbuf(sm, stage, 2);
    unsigned* B1 = smbuf(sm, stage, 3);
#pragma unroll
    for (int ks = 0; ks < 2; ks++) {
        const int wb = ks * 8;
        unsigned ah[4][4], al[4][4];
#pragma unroll
        for (int mt = 0; mt < 4; mt++) {
            const int rb = wm * 64 + mt * 16;
            ah[mt][0] = A0[(rb + r    ) * PW + wb + cq];
            ah[mt][1] = A0[(rb + 8 + r) * PW + wb + cq];
            ah[mt][2] = A0[(rb + r    ) * PW + wb + cq + 4];
            ah[mt][3] = A0[(rb + 8 + r) * PW + wb + cq + 4];
            al[mt][0] = A1[(rb + r    ) * PW + wb + cq];
            al[mt][1] = A1[(rb + 8 + r) * PW + wb + cq];
            al[mt][2] = A1[(rb + r    ) * PW + wb + cq + 4];
            al[mt][3] = A1[(rb + 8 + r) * PW + wb + cq + 4];
        }
#pragma unroll
        for (int nt = 0; nt < 4; nt++) {
            const int nb = wn * 32 + nt * 8 + r;
            const unsigned bh0 = B0[nb * PW + wb + cq];
            const unsigned bh1 = B0[nb * PW + wb + cq + 4];
            const unsigned bl0 = B1[nb * PW + wb + cq];
            const unsigned bl1 = B1[nb * PW + wb + cq + 4];
#pragma unroll
            for (int mt = 0; mt < 4; mt++) {
                mma16816(acc[mt][nt], ah[mt][0], ah[mt][1], ah[mt][2], ah[mt][3], bh0, bh1);
                mma16816(acc[mt][nt], ah[mt][0], ah[mt][1], ah[mt][2], ah[mt][3], bl0, bl1);
                mma16816(acc[mt][nt], al[mt][0], al[mt][1], al[mt][2], al[mt][3], bh0, bh1);
            }
        }
    }
}

__device__ __forceinline__ void gemm_planes(
        const unsigned* __restrict__ Xh, const unsigned* __restrict__ Xl,
        const unsigned* __restrict__ Wh, const unsigned* __restrict__ Wl,
        int m0, int n0, int tid, int wm, int wn, int r, int cq,
        unsigned* sm, float acc[4][4][4]) {
    load_chunk(sm, 0, Xh, Xl, Wh, Wl, m0, n0, 0, tid);
    load_chunk(sm, 1, Xh, Xl, Wh, Wl, m0, n0, 16, tid);
    for (int c = 0; c < 32; c++) {
        asm volatile("cp.async.wait_group 1;");
        __syncthreads();
        if (c + 2 < 32)
            load_chunk(sm, (c + 2) % NSTG, Xh, Xl, Wh, Wl, m0, n0, (c + 2) * 16, tid);
        compute_chunk(sm, c % NSTG, wm, wn, r, cq, acc);
        __syncthreads();
    }
}

// ---------------------------------------------------------------------------
// Batched q/k/v projection: grid.z selects input.
// ---------------------------------------------------------------------------
__global__ void proj_qkv(const float* __restrict__ bq,
                         const float* __restrict__ bk,
                         const float* __restrict__ bv) {
    extern __shared__ unsigned sm[];
    const int tid  = threadIdx.x;
    const int warp = tid >> 5, lane = tid & 31;
    const int wm = warp >> 2, wn = warp & 3;
    const int r = lane >> 2, cq = lane & 3;
    const int m0 = blockIdx.y * 128, n0 = blockIdx.x * 128;
    const int mode = blockIdx.z;
    const float* bias = (mode == 0) ? bq : (mode == 1) ? bk : bv;
    const float scale = (mode == 0) ? 0.125f : 1.0f;
    const unsigned* Xh = g_Xh + (size_t)mode * M_ * 512;
    const unsigned* Xl = g_Xl + (size_t)mode * M_ * 512;
    const unsigned* Wh = g_Wh + (size_t)mode * D_ * 512;
    const unsigned* Wl = g_Wl + (size_t)mode * D_ * 512;

    float acc[4][4][4];
#pragma unroll
    for (int a = 0; a < 4; a++)
#pragma unroll
        for (int b = 0; b < 4; b++)
#pragma unroll
            for (int c = 0; c < 4; c++) acc[a][b][c] = 0.f;

    gemm_planes(Xh, Xl, Wh, Wl, m0, n0, tid, wm, wn, r, cq, sm, acc);

#pragma unroll
    for (int mt = 0; mt < 4; mt++) {
#pragma unroll
        for (int nt = 0; nt < 4; nt++) {
            const int mrow = m0 + wm * 64 + mt * 16 + r;
            const int ncol = n0 + wn * 32 + nt * 8 + cq * 2;
            if (mode <= 1) {
                unsigned* ph = (mode == 0) ? g_Qh : g_Kh;
                unsigned* pl = (mode == 0) ? g_Ql : g_Kl;
#pragma unroll
                for (int half = 0; half < 2; half++) {
                    const int m = mrow + half * 8;
                    const int bb = m >> 11, ll = m & (L_ - 1);
                    const int hh = ncol >> 6, d = ncol & 63;
                    const float v0 = (acc[mt][nt][half*2+0] + bias[ncol])   * scale;
                    const float v1 = (acc[mt][nt][half*2+1] + bias[ncol+1]) * scale;
                    unsigned hi, lo;
                    split2(v0, v1, hi, lo);
                    const size_t idx = ((size_t)(bb * H_ + hh) * L_ + ll) * 32 + (d >> 1);
                    ph[idx] = hi; pl[idx] = lo;
                }
            } else {
#pragma unroll
                for (int e = 0; e < 4; e++) {
                    const int m = mrow + (e >> 1) * 8;
                    const int n = ncol + (e & 1);
                    const float v = acc[mt][nt][e] + bias[n];
                    const int bb = m >> 11, ll = m & (L_ - 1);
                    const int hh = n >> 6, d = n & 63;
                    g_V[((size_t)(bb * H_ + hh) * L_ + ll) * DH_ + d] = v;
                }
            }
        }
    }
}

// ---------------------------------------------------------------------------
// Output projection: planes slot 0 -> ext_out.
// ---------------------------------------------------------------------------
__global__ void proj_out(const float* __restrict__ bias,
                         float* __restrict__ ext_out) {
    extern __shared__ unsigned sm[];
    const int tid  = threadIdx.x;
    const int warp = tid >> 5, lane = tid & 31;
    const int wm = warp >> 2, wn = warp & 3;
    const int r = lane >> 2, cq = lane & 3;
    const int m0 = blockIdx.y * 128, n0 = blockIdx.x * 128;

    float acc[4][4][4];
#pragma unroll
    for (int a = 0; a < 4; a++)
#pragma unroll
        for (int b = 0; b < 4; b++)
#pragma unroll
            for (int c = 0; c < 4; c++) acc[a][b][c] = 0.f;

    gemm_planes(g_Xh, g_Xl, g_Wh, g_Wl, m0, n0, tid, wm, wn, r, cq, sm, acc);

#pragma unroll
    for (int mt = 0; mt < 4; mt++) {
#pragma unroll
        for (int nt = 0; nt < 4; nt++) {
            const int mrow = m0 + wm * 64 + mt * 16 + r;
            const int ncol = n0 + wn * 32 + nt * 8 + cq * 2;
#pragma unroll
            for (int e = 0; e < 4; e++) {
                const int m = mrow + (e >> 1) * 8;
                const int n = ncol + (e & 1);
                ext_out[(size_t)m * D_ + n] = acc[mt][nt][e] + bias[n];
            }
        }
    }
}

// ---------------------------------------------------------------------------
// Fused windowed attention (tighter skip margin).
// ---------------------------------------------------------------------------
__global__ void __launch_bounds__(256, 1)
attn_fused(const float* __restrict__ log_lambda, float* __restrict__ attn) {
    __shared__ unsigned Ks[2][64][36];
    __shared__ unsigned Vs[2][64][36];
    __shared__ float sred[256];
    __shared__ float sB;
    const int tid  = threadIdx.x;
    const int warp = tid >> 5, lane = tid & 31;
    const int r = lane >> 2, cq = lane & 3;
    const int z = blockIdx.y;
    const int i0 = blockIdx.x * 128;
    const int row16 = i0 + warp * 16;
    const size_t zq = (size_t)z * L_;
    const float lam = expf(log_lambda[z & (H_ - 1)]);
    const int gi0 = row16 + r, gi1 = row16 + 8 + r;

    {
        const int row = i0 + (tid >> 1);
        const size_t base = (zq + row) * 32 + (size_t)(tid & 1) * 16;
        float n2 = 0.f;
#pragma unroll
        for (int u = 0; u < 16; u++) {
            __nv_bfloat162 hb = *(const __nv_bfloat162*)&g_Qh[base + u];
            __nv_bfloat162 lb = *(const __nv_bfloat162*)&g_Ql[base + u];
            float v0 = __bfloat162float(hb.x) + __bfloat162float(lb.x);
            float v1 = __bfloat162float(hb.y) + __bfloat162float(lb.y);
            n2 += v0 * v0 + v1 * v1;
        }
        sred[tid] = n2; __syncthreads();
        float tot = 0.f;
        if (tid < 128) tot = sred[2 * tid] + sred[2 * tid + 1];
        __syncthreads();
        if (tid < 128) sred[tid] = tot;
        __syncthreads();
        for (int s = 64; s > 0; s >>= 1) {
            if (tid < s) sred[tid] = fmaxf(sred[tid], sred[tid + s]);
            __syncthreads();
        }
        if (tid == 0) sB = sqrtf(sred[0]) * g_maxK[z];
        __syncthreads();
    }
    const float bnd = sB;
    const float thr1 = 2.f * bnd + MARGIN;

    unsigned qh[4][4], ql[4][4];
#pragma unroll
    for (int ks = 0; ks < 4; ks++) {
        const size_t r0 = (zq + gi0) * 32 + ks * 8 + cq;
        const size_t r1 = (zq + gi1) * 32 + ks * 8 + cq;
        qh[ks][0] = g_Qh[r0];     qh[ks][1] = g_Qh[r1];
        qh[ks][2] = g_Qh[r0 + 4]; qh[ks][3] = g_Qh[r1 + 4];
        ql[ks][0] = g_Ql[r0];     ql[ks][1] = g_Ql[r1];
        ql[ks][2] = g_Ql[r0 + 4]; ql[ks][3] = g_Ql[r1 + 4];
    }

    float m0 = -1e30f, s0 = 0.f, m1 = -1e30f, s1 = 0.f;
    for (int c = 0; c < L_ / 64; c++) {
        const int j0 = c * 64;
        float dmin = 0.f;
        if (j0 > i0 + 127)      dmin = (float)(j0 - (i0 + 127));
        else if (i0 > j0 + 63)  dmin = (float)(i0 - (j0 + 63));
        if (lam * dmin * dmin > thr1) continue;
        __syncthreads();
#pragma unroll
        for (int t = 0; t < 2; t++) {
            const int u = t * 256 + tid;
            const int row = u >> 3, c4 = u & 7;
            *(uint4*)&Ks[0][row][c4*4] = *(const uint4*)&g_Kh[(zq + j0 + row) * 32 + c4 * 4];
            *(uint4*)&Ks[1][row][c4*4] = *(const uint4*)&g_Kl[(zq + j0 + row) * 32 + c4 * 4];
        }
        __syncthreads();

        float acc[8][4];
#pragma unroll
        for (int nt = 0; nt < 8; nt++)
#pragma unroll
            for (int e = 0; e < 4; e++) acc[nt][e] = 0.f;
#pragma unroll
        for (int ks = 0; ks < 4; ks++) {
#pragma unroll
            for (int nt = 0; nt < 8; nt++) {
                const int nb = nt * 8 + r;
                const unsigned bh0 = Ks[0][nb][ks*8+cq], bh1 = Ks[0][nb][ks*8+cq+4];
                const unsigned bl0 = Ks[1][nb][ks*8+cq], bl1 = Ks[1][nb][ks*8+cq+4];
                mma16816(acc[nt], qh[ks][0], qh[ks][1], qh[ks][2], qh[ks][3], bh0, bh1);
                mma16816(acc[nt], qh[ks][0], qh[ks][1], qh[ks][2], qh[ks][3], bl0, bl1);
                mma16816(acc[nt], ql[ks][0], ql[ks][1], ql[ks][2], ql[ks][3], bh0, bh1);
            }
        }
        float cm0 = -1e30f, cm1 = -1e30f;
#pragma unroll
        for (int nt = 0; nt < 8; nt++) {
            const int gj = j0 + nt * 8 + cq * 2;
            float d0 = (float)(gi0 - gj), d0b = (float)(gi0 - gj - 1);
            float d1 = (float)(gi1 - gj), d1b = (float)(gi1 - gj - 1);
            acc[nt][0] -= lam * d0 * d0;   acc[nt][1] -= lam * d0b * d0b;
            acc[nt][2] -= lam * d1 * d1;   acc[nt][3] -= lam * d1b * d1b;
            cm0 = fmaxf(cm0, fmaxf(acc[nt][0], acc[nt][1]));
            cm1 = fmaxf(cm1, fmaxf(acc[nt][2], acc[nt][3]));
        }
        const float nm0 = fmaxf(m0, cm0), nm1 = fmaxf(m1, cm1);
        float a0 = 0.f, a1 = 0.f;
#pragma unroll
        for (int nt = 0; nt < 8; nt++) {
            a0 += __expf(acc[nt][0] - nm0) + __expf(acc[nt][1] - nm0);
            a1 += __expf(acc[nt][2] - nm1) + __expf(acc[nt][3] - nm1);
        }
        s0 = s0 * __expf(m0 - nm0) + a0;  m0 = nm0;
        s1 = s1 * __expf(m1 - nm1) + a1;  m1 = nm1;
    }
#pragma unroll
    for (int off = 1; off <= 2; off <<= 1) {
        float mo = __shfl_xor_sync(0xffffffffu, m0, off);
        float so = __shfl_xor_sync(0xffffffffu, s0, off);
        float mn = fmaxf(m0, mo);
        s0 = s0 * __expf(m0 - mn) + so * __expf(mo - mn); m0 = mn;
        mo = __shfl_xor_sync(0xffffffffu, m1, off);
        so = __shfl_xor_sync(0xffffffffu, s1, off);
        mn = fmaxf(m1, mo);
        s1 = s1 * __expf(m1 - mn) + so * __expf(mo - mn); m1 = mn;
    }
    const float inv0 = 1.f / s0, inv1 = 1.f / s1;

    __syncthreads();
    if ((lane & 3) == 0) {
        sred[warp * 16 + r]     = m0;
        sred[warp * 16 + 8 + r] = m1;
    }
    __syncthreads();
    for (int s = 64; s > 0; s >>= 1) {
        if (tid < s) sred[tid] = fminf(sred[tid], sred[tid + s]);
        __syncthreads();
    }
    const float thr2 = bnd - sred[0] + MARGIN;

    float o[8][4];
#pragma unroll
    for (int nt = 0; nt < 8; nt++)
#pragma unroll
        for (int e = 0; e < 4; e++) o[nt][e] = 0.f;

    float* Pz = attn + (size_t)z * L_ * L_;
    const float4 z4 = make_float4(0.f, 0.f, 0.f, 0.f);
    for (int c = 0; c < L_ / 64; c++) {
        const int j0 = c * 64;
        float dmin = 0.f;
        if (j0 > i0 + 127)      dmin = (float)(j0 - (i0 + 127));
        else if (i0 > j0 + 63)  dmin = (float)(i0 - (j0 + 63));
        if (lam * dmin * dmin > thr2) {
            const int rr = i0 + (tid >> 1);
            float* dst = Pz + (size_t)rr * L_ + j0 + (tid & 1) * 32;
#pragma unroll
            for (int t = 0; t < 8; t++)
                __stcs((float4*)dst + t, z4);
            continue;
        }
        __syncthreads();
#pragma unroll
        for (int t = 0; t < 2; t++) {
            const int u = t * 256 + tid;
            const int row = u >> 3, c4 = u & 7;
            *(uint4*)&Ks[0][row][c4*4] = *(const uint4*)&g_Kh[(zq + j0 + row) * 32 + c4 * 4];
            *(uint4*)&Ks[1][row][c4*4] = *(const uint4*)&g_Kl[(zq + j0 + row) * 32 + c4 * 4];
            *(uint4*)&Vs[0][row][c4*4] = *(const uint4*)&g_Vth[((size_t)z * DH_ + row) * (L_/2) + (j0 >> 1) + c4 * 4];
            *(uint4*)&Vs[1][row][c4*4] = *(const uint4*)&g_Vtl[((size_t)z * DH_ + row) * (L_/2) + (j0 >> 1) + c4 * 4];
        }
        __syncthreads();

        float acc[8][4];
#pragma unroll
        for (int nt = 0; nt < 8; nt++)
#pragma unroll
            for (int e = 0; e < 4; e++) acc[nt][e] = 0.f;
#pragma unroll
        for (int ks = 0; ks < 4; ks++) {
#pragma unroll
            for (int nt = 0; nt < 8; nt++) {
                const int nb = nt * 8 + r;
                const unsigned bh0 = Ks[0][nb][ks*8+cq], bh1 = Ks[0][nb][ks*8+cq+4];
                const unsigned bl0 = Ks[1][nb][ks*8+cq], bl1 = Ks[1][nb][ks*8+cq+4];
                mma16816(acc[nt], qh[ks][0], qh[ks][1], qh[ks][2], qh[ks][3], bh0, bh1);
                mma16816(acc[nt], qh[ks][0], qh[ks][1], qh[ks][2], qh[ks][3], bl0, bl1);
                mma16816(acc[nt], ql[ks][0], ql[ks][1], ql[ks][2], ql[ks][3], bh0, bh1);
            }
        }
#pragma unroll
        for (int nt = 0; nt < 8; nt++) {
            const int gj = j0 + nt * 8 + cq * 2;
            float d0 = (float)(gi0 - gj), d0b = (float)(gi0 - gj - 1);
            float d1 = (float)(gi1 - gj), d1b = (float)(gi1 - gj - 1);
            acc[nt][0] = __expf(acc[nt][0] - lam * d0 * d0   - m0) * inv0;
            acc[nt][1] = __expf(acc[nt][1] - lam * d0b * d0b - m0) * inv0;
            acc[nt][2] = __expf(acc[nt][2] - lam * d1 * d1   - m1) * inv1;
            acc[nt][3] = __expf(acc[nt][3] - lam * d1b * d1b - m1) * inv1;
            __stcs((float2*)&Pz[(size_t)gi0 * L_ + gj], make_float2(acc[nt][0], acc[nt][1]));
            __stcs((float2*)&Pz[(size_t)gi1 * L_ + gj], make_float2(acc[nt][2], acc[nt][3]));
        }
#pragma unroll
        for (int ks = 0; ks < 4; ks++) {
            unsigned ah[4], al[4];
            unsigned h0, l0, h1, l1;
            split2(acc[2*ks][0],   acc[2*ks][1],   h0, l0); ah[0] = h0; al[0] = l0;
            split2(acc[2*ks][2],   acc[2*ks][3],   h0, l0); ah[1] = h0; al[1] = l0;
            split2(acc[2*ks+1][0], acc[2*ks+1][1], h1, l1); ah[2] = h1; al[2] = l1;
            split2(acc[2*ks+1][2], acc[2*ks+1][3], h1, l1); ah[3] = h1; al[3] = l1;
#pragma unroll
            for (int nt = 0; nt < 8; nt++) {
                const int nb = nt * 8 + r;
                const unsigned bh0 = Vs[0][nb][ks*8+cq], bh1 = Vs[0][nb][ks*8+cq+4];
                const unsigned bl0 = Vs[1][nb][ks*8+cq], bl1 = Vs[1][nb][ks*8+cq+4];
                mma16816(o[nt], ah[0], ah[1], ah[2], ah[3], bh0, bh1);
                mma16816(o[nt], ah[0], ah[1], ah[2], ah[3], bl0, bl1);
                mma16816(o[nt], al[0], al[1], al[2], al[3], bh0, bh1);
            }
        }
    }

    const int bb = z >> 4, hh = z & (H_ - 1);
#pragma unroll
    for (int nt = 0; nt < 8; nt++) {
        const int d = nt * 8 + cq * 2;
        *(float2*)&g_O[((size_t)bb * L_ + gi0) * D_ + hh * DH_ + d] = make_float2(o[nt][0], o[nt][1]);
        *(float2*)&g_O[((size_t)bb * L_ + gi1) * D_ + hh * DH_ + d] = make_float2(o[nt][2], o[nt][3]);
    }
}

// ---------------------------------------------------------------------------
extern "C" void kernel_launch(void* const* d_in, const int* in_sizes, int n_in,
                              void* d_out, int out_size) {
    const float* q    = (const float*)d_in[0];
    const float* k    = (const float*)d_in[1];
    const float* v    = (const float*)d_in[2];
    const float* Wq   = (const float*)d_in[3];
    const float* bq   = (const float*)d_in[4];
    const float* Wk   = (const float*)d_in[5];
    const float* bk   = (const float*)d_in[6];
    const float* Wv   = (const float*)d_in[7];
    const float* bv   = (const float*)d_in[8];
    const float* Wo   = (const float*)d_in[9];
    const float* bo   = (const float*)d_in[10];
    const float* llam = (const float*)d_in[11];

    float* out  = (float*)d_out;                       // [B, L, D]
    float* attn = out + (size_t)M_ * D_;               // [B, H, L, L]

    static bool attr_done = false;
    if (!attr_done) {
        cudaFuncSetAttribute(proj_qkv, cudaFuncAttributeMaxDynamicSharedMemorySize, SMEMP);
        cudaFuncSetAttribute(proj_out, cudaFuncAttributeMaxDynamicSharedMemorySize, SMEMP);
        attr_done = true;
    }

    const int XBLK = (M_ * D_) / 4 / 256;              // 4096
    const int WBLK = (D_ * D_) / 4 / 256;              // 1024
    const dim3 gp(D_ / 128, M_ / 128);                 // (8, 32)

    convsplit_X3<<<dim3(XBLK, 3), 256>>>(q, k, v);
    convsplit_W3<<<dim3(WBLK, 3), 256>>>(Wq, Wk, Wv);
    proj_qkv<<<dim3(D_ / 128, M_ / 128, 3), 256, SMEMP>>>(bq, bk, bv);

    vtrans_kernel<<<dim3(L_ / 128, ZN_), 256>>>();
    knorm_kernel<<<ZN_, 256>>>();

    attn_fused<<<dim3(L_ / 128, ZN_), 256>>>(llam, attn);

    convsplit_O<<<XBLK, 256>>>();
    convsplit_W3<<<dim3(WBLK, 1), 256>>>(Wo, Wo, Wo);
    proj_out<<<gp, 256, SMEMP>>>(bo, out);
}

// round 17
// speedup vs baseline: 1.0682x; 1.0682x over previous
#include <cuda_runtime.h>
#include <cuda_bf16.h>
#include <math.h>

#define B_   2
#define L_   2048
#define D_   1024
#define H_   16
#define DH_  64
#define M_   (B_*L_)      // 4096
#define ZN_  (B_*H_)      // 32
#define PW   20           // proj smem row pitch (uints): 16 data + 4 pad
#define NSTG 2            // cp.async pipeline stages (3 regressed: smem pressure)
#define SMEMP (NSTG*4*128*PW*4)
#define MARGIN 45.f       // skip-threshold margin (value-neutral vs 130, verified R14)

// ---- Scratch (no allocations) ----
__device__ unsigned g_Qh[(size_t)ZN_*L_*32];
__device__ unsigned g_Ql[(size_t)ZN_*L_*32];
__device__ unsigned g_Kh[(size_t)ZN_*L_*32];
__device__ unsigned g_Kl[(size_t)ZN_*L_*32];
__device__ float    g_V [(size_t)ZN_*L_*DH_];
__device__ unsigned g_Vth[(size_t)ZN_*DH_*(L_/2)];
__device__ unsigned g_Vtl[(size_t)ZN_*DH_*(L_/2)];
__device__ float    g_O [(size_t)M_*D_];
__device__ unsigned g_Xh[(size_t)3*M_*512];
__device__ unsigned g_Xl[(size_t)3*M_*512];
__device__ unsigned g_Wh[(size_t)3*D_*512];
__device__ unsigned g_Wl[(size_t)3*D_*512];
__device__ float    g_maxK[ZN_];

__device__ __forceinline__ void split2(float x0, float x1, unsigned &hi, unsigned &lo) {
    __nv_bfloat16 h0 = __float2bfloat16(x0);
    __nv_bfloat16 h1 = __float2bfloat16(x1);
    __nv_bfloat16 l0 = __float2bfloat16(x0 - __bfloat162float(h0));
    __nv_bfloat16 l1 = __float2bfloat16(x1 - __bfloat162float(h1));
    hi = ((unsigned)__bfloat16_as_ushort(h1) << 16) | (unsigned)__bfloat16_as_ushort(h0);
    lo = ((unsigned)__bfloat16_as_ushort(l1) << 16) | (unsigned)__bfloat16_as_ushort(l0);
}

__device__ __forceinline__ void mma16816(float* c,
        unsigned a0, unsigned a1, unsigned a2, unsigned a3,
        unsigned b0, unsigned b1) {
    asm volatile(
        "mma.sync.aligned.m16n8k16.row.col.f32.bf16.bf16.f32 "
        "{%0,%1,%2,%3},{%4,%5,%6,%7},{%8,%9},{%0,%1,%2,%3};\n"
        : "+f"(c[0]), "+f"(c[1]), "+f"(c[2]), "+f"(c[3])
        : "r"(a0), "r"(a1), "r"(a2), "r"(a3), "r"(b0), "r"(b1));
}

// ---------------------------------------------------------------------------
// fp32 -> bf16 hi/lo plane splits (device-global destinations)
// ---------------------------------------------------------------------------
__global__ void convsplit_X3(const float* __restrict__ q,
                             const float* __restrict__ k,
                             const float* __restrict__ v) {
    const float* src = (blockIdx.y == 0) ? q : (blockIdx.y == 1) ? k : v;
    const size_t off = (size_t)blockIdx.y * M_ * 512;
    const size_t i = (size_t)blockIdx.x * 256 + threadIdx.x;
    float4 a = *(const float4*)&src[i * 4];
    unsigned h0, l0, h1, l1;
    split2(a.x, a.y, h0, l0);
    split2(a.z, a.w, h1, l1);
    g_Xh[off + 2*i] = h0; g_Xh[off + 2*i+1] = h1;
    g_Xl[off + 2*i] = l0; g_Xl[off + 2*i+1] = l1;
}
__global__ void convsplit_W3(const float* __restrict__ wq,
                             const float* __restrict__ wk,
                             const float* __restrict__ wv) {
    const float* src = (blockIdx.y == 0) ? wq : (blockIdx.y == 1) ? wk : wv;
    const size_t off = (size_t)blockIdx.y * D_ * 512;
    const size_t i = (size_t)blockIdx.x * 256 + threadIdx.x;
    float4 a = *(const float4*)&src[i * 4];
    unsigned h0, l0, h1, l1;
    split2(a.x, a.y, h0, l0);
    split2(a.z, a.w, h1, l1);
    g_Wh[off + 2*i] = h0; g_Wh[off + 2*i+1] = h1;
    g_Wl[off + 2*i] = l0; g_Wl[off + 2*i+1] = l1;
}
__global__ void convsplit_O() {     // g_O -> X planes slot 0
    const size_t i = (size_t)blockIdx.x * 256 + threadIdx.x;
    float4 a = *(const float4*)&g_O[i * 4];
    unsigned h0, l0, h1, l1;
    split2(a.x, a.y, h0, l0);
    split2(a.z, a.w, h1, l1);
    g_Xh[2*i] = h0; g_Xh[2*i+1] = h1;
    g_Xl[2*i] = l0; g_Xl[2*i+1] = l1;
}

// ---------------------------------------------------------------------------
// V transpose + split:  g_V -> g_Vth/g_Vtl [z][d][l/2]
// ---------------------------------------------------------------------------
__global__ void vtrans_kernel() {
    __shared__ float sT[128][65];
    const int tid = threadIdx.x;
    const int z = blockIdx.y;
    const int l0 = blockIdx.x * 128;
    const size_t zq = (size_t)z * L_;
#pragma unroll
    for (int t = 0; t < 32; t++) {
        const int u = t * 256 + tid;
        const int l = u >> 6, d = u & 63;
        sT[l][d] = g_V[(zq + l0 + l) * DH_ + d];
    }
    __syncthreads();
#pragma unroll
    for (int t = 0; t < 16; t++) {
        const int u = t * 256 + tid;
        const int d = u >> 6, lp = u & 63;
        unsigned hi, lo;
        split2(sT[2*lp][d], sT[2*lp+1][d], hi, lo);
        const size_t idx = ((size_t)z * DH_ + d) * (L_/2) + (l0 >> 1) + lp;
        g_Vth[idx] = hi; g_Vtl[idx] = lo;
    }
}

// ---------------------------------------------------------------------------
// Per-z max K-row norm. One block per z.
// ---------------------------------------------------------------------------
__global__ void knorm_kernel() {
    __shared__ float red[256];
    const int tid = threadIdx.x;
    const int z = blockIdx.x;
    const size_t zq = (size_t)z * L_;
    float mx = 0.f;
#pragma unroll
    for (int t = 0; t < 8; t++) {
        const int row = t * 256 + tid;
        float n2 = 0.f;
        const size_t base = (zq + row) * 32;
#pragma unroll
        for (int u = 0; u < 32; u++) {
            __nv_bfloat162 hb = *(const __nv_bfloat162*)&g_Kh[base + u];
            __nv_bfloat162 lb = *(const __nv_bfloat162*)&g_Kl[base + u];
            float v0 = __bfloat162float(hb.x) + __bfloat162float(lb.x);
            float v1 = __bfloat162float(hb.y) + __bfloat162float(lb.y);
            n2 += v0 * v0 + v1 * v1;
        }
        mx = fmaxf(mx, n2);
    }
    red[tid] = mx; __syncthreads();
    for (int s = 128; s > 0; s >>= 1) {
        if (tid < s) red[tid] = fmaxf(red[tid], red[tid + s]);
        __syncthreads();
    }
    if (tid == 0) g_maxK[z] = sqrtf(red[0]);
}

// ---------------------------------------------------------------------------
// cp.async double-buffered GEMM core on pre-split planes (2-stage, R13 form).
// ---------------------------------------------------------------------------
__device__ __forceinline__ unsigned* smbuf(unsigned* sm, int stage, int arr) {
    return sm + ((stage * 4 + arr) * 128 * PW);
}

__device__ __forceinline__ void load_chunk(unsigned* sm, int stage,
        const unsigned* __restrict__ Xh, const unsigned* __restrict__ Xl,
        const unsigned* __restrict__ Wh, const unsigned* __restrict__ Wl,
        int m0, int n0, int ku, int tid) {
#pragma unroll
    for (int t = 0; t < 8; t++) {
        const int u = t * 256 + tid;
        const int arr = u >> 9, rem = u & 511;
        const int row = rem >> 2, c4 = (rem & 3) * 4;
        const unsigned* src;
        if      (arr == 0) src = &Xh[(size_t)(m0 + row) * 512 + ku + c4];
        else if (arr == 1) src = &Xl[(size_t)(m0 + row) * 512 + ku + c4];
        else if (arr == 2) src = &Wh[(size_t)(n0 + row) * 512 + ku + c4];
        else               src = &Wl[(size_t)(n0 + row) * 512 + ku + c4];
        const unsigned dst =
            (unsigned)__cvta_generic_to_shared(smbuf(sm, stage, arr) + row * PW + c4);
        asm volatile("cp.async.cg.shared.global [%0], [%1], 16;" :: "r"(dst), "l"(src));
    }
    asm volatile("cp.async.commit_group;");
}

__device__ __forceinline__ void compute_chunk(unsigned* sm, int stage,
        int wm, int wn, int r, int cq, float acc[4][4][4]) {
    unsigned* A0 = smbuf(sm, stage, 0);
    unsigned* A1 = smbuf(sm, stage, 1);
    unsigned* B0 = smbuf(sm, stage, 2);
    unsigned* B1 = smbuf(sm, stage, 3);
#pragma unroll
    for (int ks = 0; ks < 2; ks++) {
        const int wb = ks * 8;
        unsigned ah[4][4], al[4][4];
#pragma unroll
        for (int mt = 0; mt < 4; mt++) {
            const int rb = wm * 64 + mt * 16;
            ah[mt][0] = A0[(rb + r    ) * PW + wb + cq];
            ah[mt][1] = A0[(rb + 8 + r) * PW + wb + cq];
            ah[mt][2] = A0[(rb + r    ) * PW + wb + cq + 4];
            ah[mt][3] = A0[(rb + 8 + r) * PW + wb + cq + 4];
            al[mt][0] = A1[(rb + r    ) * PW + wb + cq];
            al[mt][1] = A1[(rb + 8 + r) * PW + wb + cq];
            al[mt][2] = A1[(rb + r    ) * PW + wb + cq + 4];
            al[mt][3] = A1[(rb + 8 + r) * PW + wb + cq + 4];
        }
#pragma unroll
        for (int nt = 0; nt < 4; nt++) {
            const int nb = wn * 32 + nt * 8 + r;
            const unsigned bh0 = B0[nb * PW + wb + cq];
            const unsigned bh1 = B0[nb * PW + wb + cq + 4];
            const unsigned bl0 = B1[nb * PW + wb + cq];
            const unsigned bl1 = B1[nb * PW + wb + cq + 4];
#pragma unroll
            for (int mt = 0; mt < 4; mt++) {
                mma16816(acc[mt][nt], ah[mt][0], ah[mt][1], ah[mt][2], ah[mt][3], bh0, bh1);
                mma16816(acc[mt][nt], ah[mt][0], ah[mt][1], ah[mt][2], ah[mt][3], bl0, bl1);
                mma16816(acc[mt][nt], al[mt][0], al[mt][1], al[mt][2], al[mt][3], bh0, bh1);
            }
        }
    }
}

__device__ __forceinline__ void gemm_planes(
        const unsigned* __restrict__ Xh, const unsigned* __restrict__ Xl,
        const unsigned* __restrict__ Wh, const unsigned* __restrict__ Wl,
        int m0, int n0, int tid, int wm, int wn, int r, int cq,
        unsigned* sm, float acc[4][4][4]) {
    load_chunk(sm, 0, Xh, Xl, Wh, Wl, m0, n0, 0, tid);
    for (int c = 0; c < 32; c++) {
        asm volatile("cp.async.wait_group 0;");
        __syncthreads();
        if (c + 1 < 32)
            load_chunk(sm, (c + 1) & 1, Xh, Xl, Wh, Wl, m0, n0, (c + 1) * 16, tid);
        compute_chunk(sm, c & 1, wm, wn, r, cq, acc);
        __syncthreads();
    }
}

// ---------------------------------------------------------------------------
// Batched q/k/v projection: grid.z selects input.
// ---------------------------------------------------------------------------
__global__ void proj_qkv(const float* __restrict__ bq,
                         const float* __restrict__ bk,
                         const float* __restrict__ bv) {
    extern __shared__ unsigned sm[];
    const int tid  = threadIdx.x;
    const int warp = tid >> 5, lane = tid & 31;
    const int wm = warp >> 2, wn = warp & 3;
    const int r = lane >> 2, cq = lane & 3;
    const int m0 = blockIdx.y * 128, n0 = blockIdx.x * 128;
    const int mode = blockIdx.z;
    const float* bias = (mode == 0) ? bq : (mode == 1) ? bk : bv;
    const float scale = (mode == 0) ? 0.125f : 1.0f;
    const unsigned* Xh = g_Xh + (size_t)mode * M_ * 512;
    const unsigned* Xl = g_Xl + (size_t)mode * M_ * 512;
    const unsigned* Wh = g_Wh + (size_t)mode * D_ * 512;
    const unsigned* Wl = g_Wl + (size_t)mode * D_ * 512;

    float acc[4][4][4];
#pragma unroll
    for (int a = 0; a < 4; a++)
#pragma unroll
        for (int b = 0; b < 4; b++)
#pragma unroll
            for (int c = 0; c < 4; c++) acc[a][b][c] = 0.f;

    gemm_planes(Xh, Xl, Wh, Wl, m0, n0, tid, wm, wn, r, cq, sm, acc);

#pragma unroll
    for (int mt = 0; mt < 4; mt++) {
#pragma unroll
        for (int nt = 0; nt < 4; nt++) {
            const int mrow = m0 + wm * 64 + mt * 16 + r;
            const int ncol = n0 + wn * 32 + nt * 8 + cq * 2;
            if (mode <= 1) {
                unsigned* ph = (mode == 0) ? g_Qh : g_Kh;
                unsigned* pl = (mode == 0) ? g_Ql : g_Kl;
#pragma unroll
                for (int half = 0; half < 2; half++) {
                    const int m = mrow + half * 8;
                    const int bb = m >> 11, ll = m & (L_ - 1);
                    const int hh = ncol >> 6, d = ncol & 63;
                    const float v0 = (acc[mt][nt][half*2+0] + bias[ncol])   * scale;
                    const float v1 = (acc[mt][nt][half*2+1] + bias[ncol+1]) * scale;
                    unsigned hi, lo;
                    split2(v0, v1, hi, lo);
                    const size_t idx = ((size_t)(bb * H_ + hh) * L_ + ll) * 32 + (d >> 1);
                    ph[idx] = hi; pl[idx] = lo;
                }
            } else {
#pragma unroll
                for (int e = 0; e < 4; e++) {
                    const int m = mrow + (e >> 1) * 8;
                    const int n = ncol + (e & 1);
                    const float v = acc[mt][nt][e] + bias[n];
                    const int bb = m >> 11, ll = m & (L_ - 1);
                    const int hh = n >> 6, d = n & 63;
                    g_V[((size_t)(bb * H_ + hh) * L_ + ll) * DH_ + d] = v;
                }
            }
        }
    }
}

// ---------------------------------------------------------------------------
// Output projection: planes slot 0 -> ext_out.
// ---------------------------------------------------------------------------
__global__ void proj_out(const float* __restrict__ bias,
                         float* __restrict__ ext_out) {
    extern __shared__ unsigned sm[];
    const int tid  = threadIdx.x;
    const int warp = tid >> 5, lane = tid & 31;
    const int wm = warp >> 2, wn = warp & 3;
    const int r = lane >> 2, cq = lane & 3;
    const int m0 = blockIdx.y * 128, n0 = blockIdx.x * 128;

    float acc[4][4][4];
#pragma unroll
    for (int a = 0; a < 4; a++)
#pragma unroll
        for (int b = 0; b < 4; b++)
#pragma unroll
            for (int c = 0; c < 4; c++) acc[a][b][c] = 0.f;

    gemm_planes(g_Xh, g_Xl, g_Wh, g_Wl, m0, n0, tid, wm, wn, r, cq, sm, acc);

#pragma unroll
    for (int mt = 0; mt < 4; mt++) {
#pragma unroll
        for (int nt = 0; nt < 4; nt++) {
            const int mrow = m0 + wm * 64 + mt * 16 + r;
            const int ncol = n0 + wn * 32 + nt * 8 + cq * 2;
#pragma unroll
            for (int e = 0; e < 4; e++) {
                const int m = mrow + (e >> 1) * 8;
                const int n = ncol + (e & 1);
                ext_out[(size_t)m * D_ + n] = acc[mt][nt][e] + bias[n];
            }
        }
    }
}

// ---------------------------------------------------------------------------
// Fused windowed attention (MARGIN 45 skip).
// ---------------------------------------------------------------------------
__global__ void __launch_bounds__(256, 1)
attn_fused(const float* __restrict__ log_lambda, float* __restrict__ attn) {
    __shared__ unsigned Ks[2][64][36];
    __shared__ unsigned Vs[2][64][36];
    __shared__ float sred[256];
    __shared__ float sB;
    const int tid  = threadIdx.x;
    const int warp = tid >> 5, lane = tid & 31;
    const int r = lane >> 2, cq = lane & 3;
    const int z = blockIdx.y;
    const int i0 = blockIdx.x * 128;
    const int row16 = i0 + warp * 16;
    const size_t zq = (size_t)z * L_;
    const float lam = expf(log_lambda[z & (H_ - 1)]);
    const int gi0 = row16 + r, gi1 = row16 + 8 + r;

    {
        const int row = i0 + (tid >> 1);
        const size_t base = (zq + row) * 32 + (size_t)(tid & 1) * 16;
        float n2 = 0.f;
#pragma unroll
        for (int u = 0; u < 16; u++) {
            __nv_bfloat162 hb = *(const __nv_bfloat162*)&g_Qh[base + u];
            __nv_bfloat162 lb = *(const __nv_bfloat162*)&g_Ql[base + u];
            float v0 = __bfloat162float(hb.x) + __bfloat162float(lb.x);
            float v1 = __bfloat162float(hb.y) + __bfloat162float(lb.y);
            n2 += v0 * v0 + v1 * v1;
        }
        sred[tid] = n2; __syncthreads();
        float tot = 0.f;
        if (tid < 128) tot = sred[2 * tid] + sred[2 * tid + 1];
        __syncthreads();
        if (tid < 128) sred[tid] = tot;
        __syncthreads();
        for (int s = 64; s > 0; s >>= 1) {
            if (tid < s) sred[tid] = fmaxf(sred[tid], sred[tid + s]);
            __syncthreads();
        }
        if (tid == 0) sB = sqrtf(sred[0]) * g_maxK[z];
        __syncthreads();
    }
    const float bnd = sB;
    const float thr1 = 2.f * bnd + MARGIN;

    unsigned qh[4][4], ql[4][4];
#pragma unroll
    for (int ks = 0; ks < 4; ks++) {
        const size_t r0 = (zq + gi0) * 32 + ks * 8 + cq;
        const size_t r1 = (zq + gi1) * 32 + ks * 8 + cq;
        qh[ks][0] = g_Qh[r0];     qh[ks][1] = g_Qh[r1];
        qh[ks][2] = g_Qh[r0 + 4]; qh[ks][3] = g_Qh[r1 + 4];
        ql[ks][0] = g_Ql[r0];     ql[ks][1] = g_Ql[r1];
        ql[ks][2] = g_Ql[r0 + 4]; ql[ks][3] = g_Ql[r1 + 4];
    }

    float m0 = -1e30f, s0 = 0.f, m1 = -1e30f, s1 = 0.f;
    for (int c = 0; c < L_ / 64; c++) {
        const int j0 = c * 64;
        float dmin = 0.f;
        if (j0 > i0 + 127)      dmin = (float)(j0 - (i0 + 127));
        else if (i0 > j0 + 63)  dmin = (float)(i0 - (j0 + 63));
        if (lam * dmin * dmin > thr1) continue;
        __syncthreads();
#pragma unroll
        for (int t = 0; t < 2; t++) {
            const int u = t * 256 + tid;
            const int row = u >> 3, c4 = u & 7;
            *(uint4*)&Ks[0][row][c4*4] = *(const uint4*)&g_Kh[(zq + j0 + row) * 32 + c4 * 4];
            *(uint4*)&Ks[1][row][c4*4] = *(const uint4*)&g_Kl[(zq + j0 + row) * 32 + c4 * 4];
        }
        __syncthreads();

        float acc[8][4];
#pragma unroll
        for (int nt = 0; nt < 8; nt++)
#pragma unroll
            for (int e = 0; e < 4; e++) acc[nt][e] = 0.f;
#pragma unroll
        for (int ks = 0; ks < 4; ks++) {
#pragma unroll
            for (int nt = 0; nt < 8; nt++) {
                const int nb = nt * 8 + r;
                const unsigned bh0 = Ks[0][nb][ks*8+cq], bh1 = Ks[0][nb][ks*8+cq+4];
                const unsigned bl0 = Ks[1][nb][ks*8+cq], bl1 = Ks[1][nb][ks*8+cq+4];
                mma16816(acc[nt], qh[ks][0], qh[ks][1], qh[ks][2], qh[ks][3], bh0, bh1);
                mma16816(acc[nt], qh[ks][0], qh[ks][1], qh[ks][2], qh[ks][3], bl0, bl1);
                mma16816(acc[nt], ql[ks][0], ql[ks][1], ql[ks][2], ql[ks][3], bh0, bh1);
            }
        }
        float cm0 = -1e30f, cm1 = -1e30f;
#pragma unroll
        for (int nt = 0; nt < 8; nt++) {
            const int gj = j0 + nt * 8 + cq * 2;
            float d0 = (float)(gi0 - gj), d0b = (float)(gi0 - gj - 1);
            float d1 = (float)(gi1 - gj), d1b = (float)(gi1 - gj - 1);
            acc[nt][0] -= lam * d0 * d0;   acc[nt][1] -= lam * d0b * d0b;
            acc[nt][2] -= lam * d1 * d1;   acc[nt][3] -= lam * d1b * d1b;
            cm0 = fmaxf(cm0, fmaxf(acc[nt][0], acc[nt][1]));
            cm1 = fmaxf(cm1, fmaxf(acc[nt][2], acc[nt][3]));
        }
        const float nm0 = fmaxf(m0, cm0), nm1 = fmaxf(m1, cm1);
        float a0 = 0.f, a1 = 0.f;
#pragma unroll
        for (int nt = 0; nt < 8; nt++) {
            a0 += __expf(acc[nt][0] - nm0) + __expf(acc[nt][1] - nm0);
            a1 += __expf(acc[nt][2] - nm1) + __expf(acc[nt][3] - nm1);
        }
        s0 = s0 * __expf(m0 - nm0) + a0;  m0 = nm0;
        s1 = s1 * __expf(m1 - nm1) + a1;  m1 = nm1;
    }
#pragma unroll
    for (int off = 1; off <= 2; off <<= 1) {
        float mo = __shfl_xor_sync(0xffffffffu, m0, off);
        float so = __shfl_xor_sync(0xffffffffu, s0, off);
        float mn = fmaxf(m0, mo);
        s0 = s0 * __expf(m0 - mn) + so * __expf(mo - mn); m0 = mn;
        mo = __shfl_xor_sync(0xffffffffu, m1, off);
        so = __shfl_xor_sync(0xffffffffu, s1, off);
        mn = fmaxf(m1, mo);
        s1 = s1 * __expf(m1 - mn) + so * __expf(mo - mn); m1 = mn;
    }
    const float inv0 = 1.f / s0, inv1 = 1.f / s1;

    __syncthreads();
    if ((lane & 3) == 0) {
        sred[warp * 16 + r]     = m0;
        sred[warp * 16 + 8 + r] = m1;
    }
    __syncthreads();
    for (int s = 64; s > 0; s >>= 1) {
        if (tid < s) sred[tid] = fminf(sred[tid], sred[tid + s]);
        __syncthreads();
    }
    const float thr2 = bnd - sred[0] + MARGIN;

    float o[8][4];
#pragma unroll
    for (int nt = 0; nt < 8; nt++)
#pragma unroll
        for (int e = 0; e < 4; e++) o[nt][e] = 0.f;

    float* Pz = attn + (size_t)z * L_ * L_;
    const float4 z4 = make_float4(0.f, 0.f, 0.f, 0.f);
    for (int c = 0; c < L_ / 64; c++) {
        const int j0 = c * 64;
        float dmin = 0.f;
        if (j0 > i0 + 127)      dmin = (float)(j0 - (i0 + 127));
        else if (i0 > j0 + 63)  dmin = (float)(i0 - (j0 + 63));
        if (lam * dmin * dmin > thr2) {
            const int rr = i0 + (tid >> 1);
            float* dst = Pz + (size_t)rr * L_ + j0 + (tid & 1) * 32;
#pragma unroll
            for (int t = 0; t < 8; t++)
                __stcs((float4*)dst + t, z4);
            continue;
        }
        __syncthreads();
#pragma unroll
        for (int t = 0; t < 2; t++) {
            const int u = t * 256 + tid;
            const int row = u >> 3, c4 = u & 7;
            *(uint4*)&Ks[0][row][c4*4] = *(const uint4*)&g_Kh[(zq + j0 + row) * 32 + c4 * 4];
            *(uint4*)&Ks[1][row][c4*4] = *(const uint4*)&g_Kl[(zq + j0 + row) * 32 + c4 * 4];
            *(uint4*)&Vs[0][row][c4*4] = *(const uint4*)&g_Vth[((size_t)z * DH_ + row) * (L_/2) + (j0 >> 1) + c4 * 4];
            *(uint4*)&Vs[1][row][c4*4] = *(const uint4*)&g_Vtl[((size_t)z * DH_ + row) * (L_/2) + (j0 >> 1) + c4 * 4];
        }
        __syncthreads();

        float acc[8][4];
#pragma unroll
        for (int nt = 0; nt < 8; nt++)
#pragma unroll
            for (int e = 0; e < 4; e++) acc[nt][e] = 0.f;
#pragma unroll
        for (int ks = 0; ks < 4; ks++) {
#pragma unroll
            for (int nt = 0; nt < 8; nt++) {
                const int nb = nt * 8 + r;
                const unsigned bh0 = Ks[0][nb][ks*8+cq], bh1 = Ks[0][nb][ks*8+cq+4];
                const unsigned bl0 = Ks[1][nb][ks*8+cq], bl1 = Ks[1][nb][ks*8+cq+4];
                mma16816(acc[nt], qh[ks][0], qh[ks][1], qh[ks][2], qh[ks][3], bh0, bh1);
                mma16816(acc[nt], qh[ks][0], qh[ks][1], qh[ks][2], qh[ks][3], bl0, bl1);
                mma16816(acc[nt], ql[ks][0], ql[ks][1], ql[ks][2], ql[ks][3], bh0, bh1);
            }
        }
#pragma unroll
        for (int nt = 0; nt < 8; nt++) {
            const int gj = j0 + nt * 8 + cq * 2;
            float d0 = (float)(gi0 - gj), d0b = (float)(gi0 - gj - 1);
            float d1 = (float)(gi1 - gj), d1b = (float)(gi1 - gj - 1);
            acc[nt][0] = __expf(acc[nt][0] - lam * d0 * d0   - m0) * inv0;
            acc[nt][1] = __expf(acc[nt][1] - lam * d0b * d0b - m0) * inv0;
            acc[nt][2] = __expf(acc[nt][2] - lam * d1 * d1   - m1) * inv1;
            acc[nt][3] = __expf(acc[nt][3] - lam * d1b * d1b - m1) * inv1;
            __stcs((float2*)&Pz[(size_t)gi0 * L_ + gj], make_float2(acc[nt][0], acc[nt][1]));
            __stcs((float2*)&Pz[(size_t)gi1 * L_ + gj], make_float2(acc[nt][2], acc[nt][3]));
        }
#pragma unroll
        for (int ks = 0; ks < 4; ks++) {
            unsigned ah[4], al[4];
            unsigned h0, l0, h1, l1;
            split2(acc[2*ks][0],   acc[2*ks][1],   h0, l0); ah[0] = h0; al[0] = l0;
            split2(acc[2*ks][2],   acc[2*ks][3],   h0, l0); ah[1] = h0; al[1] = l0;
            split2(acc[2*ks+1][0], acc[2*ks+1][1], h1, l1); ah[2] = h1; al[2] = l1;
            split2(acc[2*ks+1][2], acc[2*ks+1][3], h1, l1); ah[3] = h1; al[3] = l1;
#pragma unroll
            for (int nt = 0; nt < 8; nt++) {
                const int nb = nt * 8 + r;
                const unsigned bh0 = Vs[0][nb][ks*8+cq], bh1 = Vs[0][nb][ks*8+cq+4];
                const unsigned bl0 = Vs[1][nb][ks*8+cq], bl1 = Vs[1][nb][ks*8+cq+4];
                mma16816(o[nt], ah[0], ah[1], ah[2], ah[3], bh0, bh1);
                mma16816(o[nt], ah[0], ah[1], ah[2], ah[3], bl0, bl1);
                mma16816(o[nt], al[0], al[1], al[2], al[3], bh0, bh1);
            }
        }
    }

    const int bb = z >> 4, hh = z & (H_ - 1);
#pragma unroll
    for (int nt = 0; nt < 8; nt++) {
        const int d = nt * 8 + cq * 2;
        *(float2*)&g_O[((size_t)bb * L_ + gi0) * D_ + hh * DH_ + d] = make_float2(o[nt][0], o[nt][1]);
        *(float2*)&g_O[((size_t)bb * L_ + gi1) * D_ + hh * DH_ + d] = make_float2(o[nt][2], o[nt][3]);
    }
}

// ---------------------------------------------------------------------------
extern "C" void kernel_launch(void* const* d_in, const int* in_sizes, int n_in,
                              void* d_out, int out_size) {
    const float* q    = (const float*)d_in[0];
    const float* k    = (const float*)d_in[1];
    const float* v    = (const float*)d_in[2];
    const float* Wq   = (const float*)d_in[3];
    const float* bq   = (const float*)d_in[4];
    const float* Wk   = (const float*)d_in[5];
    const float* bk   = (const float*)d_in[6];
    const float* Wv   = (const float*)d_in[7];
    const float* bv   = (const float*)d_in[8];
    const float* Wo   = (const float*)d_in[9];
    const float* bo   = (const float*)d_in[10];
    const float* llam = (const float*)d_in[11];

    float* out  = (float*)d_out;                       // [B, L, D]
    float* attn = out + (size_t)M_ * D_;               // [B, H, L, L]

    cudaFuncSetAttribute(proj_qkv, cudaFuncAttributeMaxDynamicSharedMemorySize, SMEMP);
    cudaFuncSetAttribute(proj_out, cudaFuncAttributeMaxDynamicSharedMemorySize, SMEMP);

    const int XBLK = (M_ * D_) / 4 / 256;              // 4096
    const int WBLK = (D_ * D_) / 4 / 256;              // 1024
    const dim3 gp(D_ / 128, M_ / 128);                 // (8, 32)

    convsplit_X3<<<dim3(XBLK, 3), 256>>>(q, k, v);
    convsplit_W3<<<dim3(WBLK, 3), 256>>>(Wq, Wk, Wv);
    proj_qkv<<<dim3(D_ / 128, M_ / 128, 3), 256, SMEMP>>>(bq, bk, bv);

    vtrans_kernel<<<dim3(L_ / 128, ZN_), 256>>>();
    knorm_kernel<<<ZN_, 256>>>();

    attn_fused<<<dim3(L_ / 128, ZN_), 256>>>(llam, attn);

    convsplit_O<<<XBLK, 256>>>();
    convsplit_W3<<<dim3(WBLK, 1), 256>>>(Wo, Wo, Wo);
    proj_out<<<gp, 256, SMEMP>>>(bo, out);
}